// round 5
// baseline (speedup 1.0000x reference)
#include <cuda_runtime.h>
#include <cuda_bf16.h>
#include <cstdint>

#define DI __device__ __forceinline__

static constexpr int BB = 64, NN = 256, HH = 1024, OO = 768;

// ---- static device scratch (no allocs allowed) ----
__device__ __align__(256) float g_kt[(size_t)BB * HH * OO];   // kt[b][h][o]
__device__ __align__(256) float g_w [(size_t)BB * NN * OO];   // weight[b][n][o]
__device__ __align__(256) float g_pre[(size_t)BB * NN * HH];  // pre-LN [b][n][h]

// ---- helpers ----
DI uint32_t s2u(const void* p) {
    uint32_t a;
    asm("{ .reg .u64 t; cvta.to.shared.u64 t, %1; cvt.u32.u64 %0, t; }" : "=r"(a) : "l"(p));
    return a;
}
DI void ldx4(uint32_t r[4], uint32_t addr) {
    asm volatile("ldmatrix.sync.aligned.m8n8.x4.shared.b16 {%0,%1,%2,%3}, [%4];"
        : "=r"(r[0]), "=r"(r[1]), "=r"(r[2]), "=r"(r[3]) : "r"(addr));
}
DI void mma16816(float c[4], const uint32_t a[4], const uint32_t b[2]) {
    asm volatile("mma.sync.aligned.m16n8k16.row.col.f32.bf16.bf16.f32 "
        "{%0,%1,%2,%3}, {%4,%5,%6,%7}, {%8,%9}, {%0,%1,%2,%3};"
        : "+f"(c[0]), "+f"(c[1]), "+f"(c[2]), "+f"(c[3])
        : "r"(a[0]), "r"(a[1]), "r"(a[2]), "r"(a[3]), "r"(b[0]), "r"(b[1]));
}
DI uint32_t pk(__nv_bfloat16 a, __nv_bfloat16 b) {
    return (uint32_t)__bfloat16_as_ushort(a) | ((uint32_t)__bfloat16_as_ushort(b) << 16);
}

// smem stage layout: Ah(16K) Al(16K) Bh(16K) Bl(16K) = 64KB per stage, 2 stages.
static constexpr int STG = 65536;
static constexpr int SMEM_TOTAL = 2 * STG;  // 131072; epilogue reuses (needs 66048)

// Load a 128x64 fp32 tile, split to bf16 hi/lo, store swizzled.
DI void load_tile(const float* __restrict__ g, int lda, char* H, char* L, int tid) {
#pragma unroll
    for (int i = 0; i < 4; i++) {
        int q = tid + 256 * i, row = q >> 3, ck = q & 7;
        const float* p = g + (size_t)row * lda + ck * 8;
        float4 v0 = *(const float4*)p;
        float4 v1 = *(const float4*)(p + 4);
        float f[8] = {v0.x, v0.y, v0.z, v0.w, v1.x, v1.y, v1.z, v1.w};
        uint32_t hp[4], lp[4];
#pragma unroll
        for (int j = 0; j < 4; j++) {
            __nv_bfloat16 h0 = __float2bfloat16(f[2 * j]);
            __nv_bfloat16 h1 = __float2bfloat16(f[2 * j + 1]);
            __nv_bfloat16 l0 = __float2bfloat16(f[2 * j] - __bfloat162float(h0));
            __nv_bfloat16 l1 = __float2bfloat16(f[2 * j + 1] - __bfloat162float(h1));
            hp[j] = pk(h0, h1);
            lp[j] = pk(l0, l1);
        }
        int off = row * 128 + ((ck ^ (row & 7)) << 4);
        *(uint4*)(H + off) = make_uint4(hp[0], hp[1], hp[2], hp[3]);
        *(uint4*)(L + off) = make_uint4(lp[0], lp[1], lp[2], lp[3]);
    }
}

// One 64-wide K stage of split-bf16 mma: acc += Ah.Bh + Ah.Bl + Al.Bh
DI void compute_stage(uint32_t smb, int buf, int wr, int wc, int lane, float acc[4][4][4]) {
    uint32_t Ah = smb + buf * STG;
    uint32_t Al = Ah + 16384, Bh = Ah + 32768, Bl = Ah + 49152;
    const int ar = wr * 64 + (lane & 15);
    const int br = wc * 32 + (lane & 7) + ((lane & 16) >> 1);
    const int ax = lane & 7;
#pragma unroll
    for (int kk = 0; kk < 4; kk++) {
        const int ac = kk * 2 + (lane >> 4);
        const int bc = kk * 2 + ((lane >> 3) & 1);
        uint32_t ah[4][4], al[4][4], bh[4][2], bl[4][2];
#pragma unroll
        for (int mt = 0; mt < 4; mt++) {
            uint32_t off = (uint32_t)(ar + mt * 16) * 128 + (uint32_t)((ac ^ ax) << 4);
            ldx4(ah[mt], Ah + off);
            ldx4(al[mt], Al + off);
        }
#pragma unroll
        for (int p = 0; p < 2; p++) {
            uint32_t off = (uint32_t)(br + p * 16) * 128 + (uint32_t)((bc ^ ax) << 4);
            uint32_t q[4];
            ldx4(q, Bh + off);
            bh[2 * p][0] = q[0]; bh[2 * p][1] = q[1];
            bh[2 * p + 1][0] = q[2]; bh[2 * p + 1][1] = q[3];
            ldx4(q, Bl + off);
            bl[2 * p][0] = q[0]; bl[2 * p][1] = q[1];
            bl[2 * p + 1][0] = q[2]; bl[2 * p + 1][1] = q[3];
        }
#pragma unroll
        for (int mt = 0; mt < 4; mt++)
#pragma unroll
            for (int nt = 0; nt < 4; nt++) mma16816(acc[mt][nt], ah[mt], bh[nt]);
#pragma unroll
        for (int mt = 0; mt < 4; mt++)
#pragma unroll
            for (int nt = 0; nt < 4; nt++) mma16816(acc[mt][nt], ah[mt], bl[nt]);
#pragma unroll
        for (int mt = 0; mt < 4; mt++)
#pragma unroll
            for (int nt = 0; nt < 4; nt++) mma16816(acc[mt][nt], al[mt], bh[nt]);
    }
}

// D[m][n] = A[m,:].B[n,:] (+bias[m]); out[n][m] = D (m-contiguous store).
template <bool BIAS>
__global__ void __launch_bounds__(256, 1)
gemm_kernel(const float* __restrict__ A, int lda, size_t Ab,
            const float* __restrict__ B, int ldb, size_t Bb,
            const float* __restrict__ bias,
            float* __restrict__ out, int ldo, size_t Ob, int NS) {
    extern __shared__ char sm[];
    uint32_t smb = s2u(sm);
    const int m0 = blockIdx.x * 128, n0 = blockIdx.y * 128, b = blockIdx.z;
    const int tid = threadIdx.x, w = tid >> 5, lane = tid & 31;
    const int wr = w >> 2, wc = w & 3;
    const float* Abase = A + Ab * b + (size_t)m0 * lda;
    const float* Bbase = B + Bb * b + (size_t)n0 * ldb;

    float acc[4][4][4];
#pragma unroll
    for (int i = 0; i < 4; i++)
#pragma unroll
        for (int j = 0; j < 4; j++)
#pragma unroll
            for (int c = 0; c < 4; c++) acc[i][j][c] = 0.f;

    load_tile(Abase, lda, sm, sm + 16384, tid);
    load_tile(Bbase, ldb, sm + 32768, sm + 49152, tid);
    __syncthreads();

    for (int s = 0; s < NS; s++) {
        if (s + 1 < NS) {
            char* nb = sm + ((s + 1) & 1) * STG;
            load_tile(Abase + (s + 1) * 64, lda, nb, nb + 16384, tid);
            load_tile(Bbase + (s + 1) * 64, ldb, nb + 32768, nb + 49152, tid);
        }
        compute_stage(smb, s & 1, wr, wc, lane, acc);
        __syncthreads();
    }

    // epilogue: transpose through padded smem, write out[n][m] m-contiguous
    float* eps = (float*)sm;
#pragma unroll
    for (int mt = 0; mt < 4; mt++)
#pragma unroll
        for (int nt = 0; nt < 4; nt++) {
            int m = wr * 64 + mt * 16 + (lane >> 2);
            int n = wc * 32 + nt * 8 + (lane & 3) * 2;
            eps[m * 129 + n]           = acc[mt][nt][0];
            eps[m * 129 + n + 1]       = acc[mt][nt][1];
            eps[(m + 8) * 129 + n]     = acc[mt][nt][2];
            eps[(m + 8) * 129 + n + 1] = acc[mt][nt][3];
        }
    __syncthreads();

    const int m = tid & 127, nh = (tid >> 7) * 64;
    const float bv = BIAS ? bias[m0 + m] : 0.f;
    float* obase = out + Ob * b + (size_t)n0 * ldo + m0 + m;
#pragma unroll 8
    for (int j = 0; j < 64; j++) {
        int n = nh + j;
        obase[(size_t)n * ldo] = eps[m * 129 + n] + bv;
    }
}

// kt[b][h][o] = k[b][o/3][h + o%3 - 1], zero-padded. smem transpose for coalescing.
__global__ void __launch_bounds__(256)
ktbuild_kernel(const float* __restrict__ k) {
    __shared__ float sm[64][68];
    const int b = blockIdx.z, nin0 = blockIdx.x * 64, h0 = blockIdx.y * 64;
    const int tid = threadIdx.x;
    for (int idx = tid; idx < 64 * 66; idx += 256) {
        int i = idx / 66, c = idx % 66, h = h0 + c - 1;
        sm[i][c] = (h >= 0 && h < HH) ? k[((size_t)b * NN + nin0 + i) * HH + h] : 0.f;
    }
    __syncthreads();
    float* dst = g_kt + ((size_t)b * HH + h0) * OO + 3 * nin0;
    for (int idx = tid; idx < 64 * 192; idx += 256) {
        int j = idx / 192, c = idx % 192, i = c / 3, d = c - i * 3;
        dst[(size_t)j * OO + c] = sm[i][j + d];
    }
}

// LayerNorm over H per (b,n) row
__global__ void __launch_bounds__(256)
ln_kernel(const float* __restrict__ gamma, const float* __restrict__ beta,
          float* __restrict__ out) {
    const int row = blockIdx.x, tid = threadIdx.x;
    const float* x = g_pre + (size_t)row * HH;
    float4 v = *(const float4*)(x + tid * 4);
    float s = v.x + v.y + v.z + v.w;
    float q = v.x * v.x + v.y * v.y + v.z * v.z + v.w * v.w;
#pragma unroll
    for (int o = 16; o; o >>= 1) {
        s += __shfl_xor_sync(0xFFFFFFFFu, s, o);
        q += __shfl_xor_sync(0xFFFFFFFFu, q, o);
    }
    __shared__ float ss[8], sq[8], red[2];
    if ((tid & 31) == 0) { ss[tid >> 5] = s; sq[tid >> 5] = q; }
    __syncthreads();
    if (tid == 0) {
        float S = 0.f, Q = 0.f;
#pragma unroll
        for (int i = 0; i < 8; i++) { S += ss[i]; Q += sq[i]; }
        float mu = S * (1.0f / HH);
        float var = Q * (1.0f / HH) - mu * mu;
        red[0] = mu;
        red[1] = rsqrtf(var + 1e-5f);
    }
    __syncthreads();
    const float mu = red[0], rinv = red[1];
    const int h = tid * 4;
    float4 g = *(const float4*)(gamma + h);
    float4 bt = *(const float4*)(beta + h);
    float4 y;
    y.x = (v.x - mu) * rinv * g.x + bt.x;
    y.y = (v.y - mu) * rinv * g.y + bt.y;
    y.z = (v.z - mu) * rinv * g.z + bt.z;
    y.w = (v.w - mu) * rinv * g.w + bt.w;
    *(float4*)(out + (size_t)row * HH + h) = y;
}

extern "C" void kernel_launch(void* const* d_in, const int* in_sizes, int n_in,
                              void* d_out, int out_size) {
    const float* f  = (const float*)d_in[0];
    const float* k  = (const float*)d_in[1];
    const float* W  = (const float*)d_in[2];
    const float* bl = (const float*)d_in[3];
    const float* gm = (const float*)d_in[4];
    const float* bt = (const float*)d_in[5];
    float* out = (float*)d_out;

    float *ktp, *wp, *prep;
    cudaGetSymbolAddress((void**)&ktp,  g_kt);
    cudaGetSymbolAddress((void**)&wp,   g_w);
    cudaGetSymbolAddress((void**)&prep, g_pre);

    cudaFuncSetAttribute(gemm_kernel<true>,  cudaFuncAttributeMaxDynamicSharedMemorySize, SMEM_TOTAL);
    cudaFuncSetAttribute(gemm_kernel<false>, cudaFuncAttributeMaxDynamicSharedMemorySize, SMEM_TOTAL);

    // kt[b][h][o] build
    ktbuild_kernel<<<dim3(4, 16, BB), 256>>>(k);

    // GEMM1: w[b][n][o] = f[b,n,:].W_lin[o,:] + b_lin[o]
    gemm_kernel<true><<<dim3(OO / 128, NN / 128, BB), 256, SMEM_TOTAL>>>(
        W, HH, 0, f, HH, (size_t)NN * HH, bl, wp, OO, (size_t)NN * OO, HH / 64);

    // GEMM2: pre[b][n][h] = kt[b,h,:].w[b,n,:]
    gemm_kernel<false><<<dim3(HH / 128, NN / 128, BB), 256, SMEM_TOTAL>>>(
        ktp, OO, (size_t)HH * OO, wp, OO, (size_t)NN * OO, nullptr,
        prep, HH, (size_t)NN * HH, OO / 64);

    ln_kernel<<<BB * NN, 256>>>(gm, bt, out);
}

// round 9
// speedup vs baseline: 1.3428x; 1.3428x over previous
#include <cuda_runtime.h>
#include <cuda_fp16.h>
#include <cstdint>

#define DI __device__ __forceinline__

static constexpr int BB = 64, NN = 256, HH = 1024, OO = 768;

// ---- static device scratch (no allocs allowed) ----
__device__ __align__(256) __half g_kt_hi[(size_t)BB * HH * OO];  // kt hi [b][h][o]
__device__ __align__(256) __half g_w_hi[(size_t)BB * NN * OO];   // weight hi [b][n][o]
__device__ __align__(256) __half g_w_lo[(size_t)BB * NN * OO];   // weight lo [b][n][o]
__device__ __align__(256) float  g_pre[(size_t)BB * NN * HH];    // pre-LN [b][n][h]

// ---- helpers ----
DI uint32_t s2u(const void* p) {
    uint32_t a;
    asm("{ .reg .u64 t; cvta.to.shared.u64 t, %1; cvt.u32.u64 %0, t; }" : "=r"(a) : "l"(p));
    return a;
}
DI void ldx4(uint32_t r[4], uint32_t addr) {
    asm volatile("ldmatrix.sync.aligned.m8n8.x4.shared.b16 {%0,%1,%2,%3}, [%4];"
        : "=r"(r[0]), "=r"(r[1]), "=r"(r[2]), "=r"(r[3]) : "r"(addr));
}
DI void mma16816(float c[4], const uint32_t a[4], const uint32_t b[2]) {
    asm volatile("mma.sync.aligned.m16n8k16.row.col.f32.f16.f16.f32 "
        "{%0,%1,%2,%3}, {%4,%5,%6,%7}, {%8,%9}, {%0,%1,%2,%3};"
        : "+f"(c[0]), "+f"(c[1]), "+f"(c[2]), "+f"(c[3])
        : "r"(a[0]), "r"(a[1]), "r"(a[2]), "r"(a[3]), "r"(b[0]), "r"(b[1]));
}
DI uint32_t pkh(__half a, __half b) {
    return (uint32_t)__half_as_ushort(a) | ((uint32_t)__half_as_ushort(b) << 16);
}

// smem stage: Ah(16K) Bh(16K) Bl(16K) = 48KB/stage, 2 stages = 96KB.
static constexpr int STG = 49152;
static constexpr int SMEM_TOTAL = 2 * STG;  // 98304; epilogue reuse needs 66048

// fp32 128x64 tile -> fp16 hi only, swizzled store
DI void load_f32_hi(const float* __restrict__ g, int lda, char* H, int tid) {
#pragma unroll
    for (int i = 0; i < 4; i++) {
        int q = tid + 256 * i, row = q >> 3, ck = q & 7;
        const float* p = g + (size_t)row * lda + ck * 8;
        float4 v0 = *(const float4*)p;
        float4 v1 = *(const float4*)(p + 4);
        float fv[8] = {v0.x, v0.y, v0.z, v0.w, v1.x, v1.y, v1.z, v1.w};
        uint32_t hp[4];
#pragma unroll
        for (int j = 0; j < 4; j++)
            hp[j] = pkh(__float2half_rn(fv[2 * j]), __float2half_rn(fv[2 * j + 1]));
        int off = row * 128 + ((ck ^ (row & 7)) << 4);
        *(uint4*)(H + off) = make_uint4(hp[0], hp[1], hp[2], hp[3]);
    }
}

// fp32 128x64 tile -> fp16 hi + lo, swizzled
DI void load_f32_hilo(const float* __restrict__ g, int lda, char* H, char* L, int tid) {
#pragma unroll
    for (int i = 0; i < 4; i++) {
        int q = tid + 256 * i, row = q >> 3, ck = q & 7;
        const float* p = g + (size_t)row * lda + ck * 8;
        float4 v0 = *(const float4*)p;
        float4 v1 = *(const float4*)(p + 4);
        float fv[8] = {v0.x, v0.y, v0.z, v0.w, v1.x, v1.y, v1.z, v1.w};
        uint32_t hp[4], lp[4];
#pragma unroll
        for (int j = 0; j < 4; j++) {
            __half h0 = __float2half_rn(fv[2 * j]);
            __half h1 = __float2half_rn(fv[2 * j + 1]);
            __half l0 = __float2half_rn(fv[2 * j] - __half2float(h0));
            __half l1 = __float2half_rn(fv[2 * j + 1] - __half2float(h1));
            hp[j] = pkh(h0, h1);
            lp[j] = pkh(l0, l1);
        }
        int off = row * 128 + ((ck ^ (row & 7)) << 4);
        *(uint4*)(H + off) = make_uint4(hp[0], hp[1], hp[2], hp[3]);
        *(uint4*)(L + off) = make_uint4(lp[0], lp[1], lp[2], lp[3]);
    }
}

// fp16 128x64 tile -> swizzled copy
DI void load_h16(const __half* __restrict__ g, int lda, char* D, int tid) {
#pragma unroll
    for (int i = 0; i < 4; i++) {
        int q = tid + 256 * i, row = q >> 3, ck = q & 7;
        int off = row * 128 + ((ck ^ (row & 7)) << 4);
        *(uint4*)(D + off) = *(const uint4*)(g + (size_t)row * lda + ck * 8);
    }
}

// One 64-wide K stage, 2-pass: acc += Ah.Bh + Ah.Bl
DI void compute_stage2(uint32_t smb, int buf, int wr, int wc, int lane, float acc[4][4][4]) {
    uint32_t Ah = smb + buf * STG;
    uint32_t Bh = Ah + 16384, Bl = Ah + 32768;
    const int ar = wr * 64 + (lane & 15);
    const int br = wc * 32 + (lane & 7) + ((lane & 16) >> 1);
    const int ax = lane & 7;
#pragma unroll
    for (int kk = 0; kk < 4; kk++) {
        const int ac = kk * 2 + (lane >> 4);
        const int bc = kk * 2 + ((lane >> 3) & 1);
        uint32_t ah[4][4], bh[4][2], bl[4][2];
#pragma unroll
        for (int mt = 0; mt < 4; mt++)
            ldx4(ah[mt], Ah + (uint32_t)(ar + mt * 16) * 128 + (uint32_t)((ac ^ ax) << 4));
#pragma unroll
        for (int p = 0; p < 2; p++) {
            uint32_t off = (uint32_t)(br + p * 16) * 128 + (uint32_t)((bc ^ ax) << 4);
            uint32_t q[4];
            ldx4(q, Bh + off);
            bh[2 * p][0] = q[0]; bh[2 * p][1] = q[1];
            bh[2 * p + 1][0] = q[2]; bh[2 * p + 1][1] = q[3];
            ldx4(q, Bl + off);
            bl[2 * p][0] = q[0]; bl[2 * p][1] = q[1];
            bl[2 * p + 1][0] = q[2]; bl[2 * p + 1][1] = q[3];
        }
#pragma unroll
        for (int mt = 0; mt < 4; mt++)
#pragma unroll
            for (int nt = 0; nt < 4; nt++) mma16816(acc[mt][nt], ah[mt], bh[nt]);
#pragma unroll
        for (int mt = 0; mt < 4; mt++)
#pragma unroll
            for (int nt = 0; nt < 4; nt++) mma16816(acc[mt][nt], ah[mt], bl[nt]);
    }
}

// shared epilogue: acc -> padded smem transpose
DI void epilogue_to_smem(float* eps, int wr, int wc, int lane, float acc[4][4][4]) {
#pragma unroll
    for (int mt = 0; mt < 4; mt++)
#pragma unroll
        for (int nt = 0; nt < 4; nt++) {
            int m = wr * 64 + mt * 16 + (lane >> 2);
            int n = wc * 32 + nt * 8 + (lane & 3) * 2;
            eps[m * 129 + n]           = acc[mt][nt][0];
            eps[m * 129 + n + 1]       = acc[mt][nt][1];
            eps[(m + 8) * 129 + n]     = acc[mt][nt][2];
            eps[(m + 8) * 129 + n + 1] = acc[mt][nt][3];
        }
}

// ===== GEMM1: w[b][n][o] = f[b,n,:].W_lin[o,:] + b_lin[o]; out split fp16 hi/lo =====
__global__ void __launch_bounds__(256, 1)
gemm1_kernel(const float* __restrict__ W, const float* __restrict__ f,
             const float* __restrict__ bias) {
    extern __shared__ char sm[];
    uint32_t smb = s2u(sm);
    const int m0 = blockIdx.x * 128, n0 = blockIdx.y * 128, b = blockIdx.z;
    const int tid = threadIdx.x, w = tid >> 5, lane = tid & 31;
    const int wr = w >> 2, wc = w & 3;
    const float* Abase = W + (size_t)m0 * HH;
    const float* Bbase = f + ((size_t)b * NN + n0) * HH;

    float acc[4][4][4];
#pragma unroll
    for (int i = 0; i < 4; i++)
#pragma unroll
        for (int j = 0; j < 4; j++)
#pragma unroll
            for (int c = 0; c < 4; c++) acc[i][j][c] = 0.f;

    load_f32_hi(Abase, HH, sm, tid);
    load_f32_hilo(Bbase, HH, sm + 16384, sm + 32768, tid);
    __syncthreads();

    const int NS = HH / 64;  // 16
    for (int s = 0; s < NS; s++) {
        if (s + 1 < NS) {
            char* nb = sm + ((s + 1) & 1) * STG;
            load_f32_hi(Abase + (s + 1) * 64, HH, nb, tid);
            load_f32_hilo(Bbase + (s + 1) * 64, HH, nb + 16384, nb + 32768, tid);
        }
        compute_stage2(smb, s & 1, wr, wc, lane, acc);
        __syncthreads();
    }

    float* eps = (float*)sm;
    epilogue_to_smem(eps, wr, wc, lane, acc);
    __syncthreads();

    const int m = tid & 127, nh = (tid >> 7) * 64;
    const float bv = bias[m0 + m];
    __half* oh = g_w_hi + ((size_t)b * NN + n0) * OO + m0 + m;
    __half* ol = g_w_lo + ((size_t)b * NN + n0) * OO + m0 + m;
#pragma unroll 8
    for (int j = 0; j < 64; j++) {
        int n = nh + j;
        float v = eps[m * 129 + n] + bv;
        __half h = __float2half_rn(v);
        __half l = __float2half_rn(v - __half2float(h));
        oh[(size_t)n * OO] = h;
        ol[(size_t)n * OO] = l;
    }
}

// ===== GEMM2: pre[b][n][h] = kt_hi[b,h,:].(w_hi+w_lo)[b,n,:] =====
__global__ void __launch_bounds__(256, 1)
gemm2_kernel() {
    extern __shared__ char sm[];
    uint32_t smb = s2u(sm);
    const int m0 = blockIdx.x * 128, n0 = blockIdx.y * 128, b = blockIdx.z;
    const int tid = threadIdx.x, w = tid >> 5, lane = tid & 31;
    const int wr = w >> 2, wc = w & 3;
    const __half* Abase = g_kt_hi + ((size_t)b * HH + m0) * OO;
    const __half* Bh = g_w_hi + ((size_t)b * NN + n0) * OO;
    const __half* Bl = g_w_lo + ((size_t)b * NN + n0) * OO;

    float acc[4][4][4];
#pragma unroll
    for (int i = 0; i < 4; i++)
#pragma unroll
        for (int j = 0; j < 4; j++)
#pragma unroll
            for (int c = 0; c < 4; c++) acc[i][j][c] = 0.f;

    load_h16(Abase, OO, sm, tid);
    load_h16(Bh, OO, sm + 16384, tid);
    load_h16(Bl, OO, sm + 32768, tid);
    __syncthreads();

    const int NS = OO / 64;  // 12
    for (int s = 0; s < NS; s++) {
        if (s + 1 < NS) {
            char* nb = sm + ((s + 1) & 1) * STG;
            load_h16(Abase + (s + 1) * 64, OO, nb, tid);
            load_h16(Bh + (s + 1) * 64, OO, nb + 16384, tid);
            load_h16(Bl + (s + 1) * 64, OO, nb + 32768, tid);
        }
        compute_stage2(smb, s & 1, wr, wc, lane, acc);
        __syncthreads();
    }

    float* eps = (float*)sm;
    epilogue_to_smem(eps, wr, wc, lane, acc);
    __syncthreads();

    const int m = tid & 127, nh = (tid >> 7) * 64;
    float* ob = g_pre + ((size_t)b * NN + n0) * HH + m0 + m;
#pragma unroll 8
    for (int j = 0; j < 64; j++) {
        int n = nh + j;
        ob[(size_t)n * HH] = eps[m * 129 + n];
    }
}

// kt_hi[b][h][o] = fp16( k[b][o/3][h + o%3 - 1] ), zero-padded.
__global__ void __launch_bounds__(256)
ktbuild_kernel(const float* __restrict__ k) {
    __shared__ float sm[64][68];
    const int b = blockIdx.z, nin0 = blockIdx.x * 64, h0 = blockIdx.y * 64;
    const int tid = threadIdx.x;
    for (int idx = tid; idx < 64 * 66; idx += 256) {
        int i = idx / 66, c = idx % 66, h = h0 + c - 1;
        sm[i][c] = (h >= 0 && h < HH) ? k[((size_t)b * NN + nin0 + i) * HH + h] : 0.f;
    }
    __syncthreads();
    __half* dst = g_kt_hi + ((size_t)b * HH + h0) * OO + 3 * nin0;
    for (int idx = tid; idx < 64 * 96; idx += 256) {
        int j = idx / 96, p = idx % 96;
        int c0 = 2 * p, c1 = c0 + 1;
        int i0 = c0 / 3, d0 = c0 - 3 * i0;
        int i1 = c1 / 3, d1 = c1 - 3 * i1;
        *(__half2*)(dst + (size_t)j * OO + c0) =
            __floats2half2_rn(sm[i0][j + d0], sm[i1][j + d1]);
    }
}

// LayerNorm over H per (b,n) row
__global__ void __launch_bounds__(256)
ln_kernel(const float* __restrict__ gamma, const float* __restrict__ beta,
          float* __restrict__ out) {
    const int row = blockIdx.x, tid = threadIdx.x;
    const float* x = g_pre + (size_t)row * HH;
    float4 v = *(const float4*)(x + tid * 4);
    float s = v.x + v.y + v.z + v.w;
    float q = v.x * v.x + v.y * v.y + v.z * v.z + v.w * v.w;
#pragma unroll
    for (int o = 16; o; o >>= 1) {
        s += __shfl_xor_sync(0xFFFFFFFFu, s, o);
        q += __shfl_xor_sync(0xFFFFFFFFu, q, o);
    }
    __shared__ float ss[8], sq[8], red[2];
    if ((tid & 31) == 0) { ss[tid >> 5] = s; sq[tid >> 5] = q; }
    __syncthreads();
    if (tid == 0) {
        float S = 0.f, Q = 0.f;
#pragma unroll
        for (int i = 0; i < 8; i++) { S += ss[i]; Q += sq[i]; }
        float mu = S * (1.0f / HH);
        float var = Q * (1.0f / HH) - mu * mu;
        red[0] = mu;
        red[1] = rsqrtf(var + 1e-5f);
    }
    __syncthreads();
    const float mu = red[0], rinv = red[1];
    const int h = tid * 4;
    float4 g = *(const float4*)(gamma + h);
    float4 bt = *(const float4*)(beta + h);
    float4 y;
    y.x = (v.x - mu) * rinv * g.x + bt.x;
    y.y = (v.y - mu) * rinv * g.y + bt.y;
    y.z = (v.z - mu) * rinv * g.z + bt.z;
    y.w = (v.w - mu) * rinv * g.w + bt.w;
    *(float4*)(out + (size_t)row * HH + h) = y;
}

extern "C" void kernel_launch(void* const* d_in, const int* in_sizes, int n_in,
                              void* d_out, int out_size) {
    const float* f  = (const float*)d_in[0];
    const float* k  = (const float*)d_in[1];
    const float* W  = (const float*)d_in[2];
    const float* bl = (const float*)d_in[3];
    const float* gm = (const float*)d_in[4];
    const float* bt = (const float*)d_in[5];
    float* out = (float*)d_out;

    cudaFuncSetAttribute(gemm1_kernel, cudaFuncAttributeMaxDynamicSharedMemorySize, SMEM_TOTAL);
    cudaFuncSetAttribute(gemm2_kernel, cudaFuncAttributeMaxDynamicSharedMemorySize, SMEM_TOTAL);

    ktbuild_kernel<<<dim3(4, 16, BB), 256>>>(k);
    gemm1_kernel<<<dim3(OO / 128, NN / 128, BB), 256, SMEM_TOTAL>>>(W, f, bl);
    gemm2_kernel<<<dim3(HH / 128, NN / 128, BB), 256, SMEM_TOTAL>>>();
    ln_kernel<<<BB * NN, 256>>>(gm, bt, out);
}

// round 10
// speedup vs baseline: 2.2719x; 1.6919x over previous
#include <cuda_runtime.h>
#include <cuda_fp16.h>
#include <cstdint>

#define DI __device__ __forceinline__

static constexpr int BB = 64, NN = 256, HH = 1024, OO = 768;

// ---- static device scratch (no allocs allowed) ----
__device__ __align__(256) __half g_kt_hi[(size_t)BB * HH * OO];  // kt [b][h][o]
__device__ __align__(256) __half g_w_hi[(size_t)BB * NN * OO];   // weight [b][n][o]
__device__ __align__(256) float  g_pre[(size_t)BB * NN * HH];    // pre-LN [b][n][h]

// ---- helpers ----
DI uint32_t s2u(const void* p) {
    uint32_t a;
    asm("{ .reg .u64 t; cvta.to.shared.u64 t, %1; cvt.u32.u64 %0, t; }" : "=r"(a) : "l"(p));
    return a;
}
DI void ldx4(uint32_t r[4], uint32_t addr) {
    asm volatile("ldmatrix.sync.aligned.m8n8.x4.shared.b16 {%0,%1,%2,%3}, [%4];"
        : "=r"(r[0]), "=r"(r[1]), "=r"(r[2]), "=r"(r[3]) : "r"(addr));
}
DI void mma16816(float c[4], const uint32_t a[4], const uint32_t b[2]) {
    asm volatile("mma.sync.aligned.m16n8k16.row.col.f32.f16.f16.f32 "
        "{%0,%1,%2,%3}, {%4,%5,%6,%7}, {%8,%9}, {%0,%1,%2,%3};"
        : "+f"(c[0]), "+f"(c[1]), "+f"(c[2]), "+f"(c[3])
        : "r"(a[0]), "r"(a[1]), "r"(a[2]), "r"(a[3]), "r"(b[0]), "r"(b[1]));
}
DI uint32_t pkh(__half a, __half b) {
    return (uint32_t)__half_as_ushort(a) | ((uint32_t)__half_as_ushort(b) << 16);
}

// smem stage: Ah(16K) Bh(16K) = 32KB/stage, 2 stages = 64KB.
// Epilogue transpose reuses smem and needs 128*129*4 = 66048 B -> total 66048.
static constexpr int STG = 32768;
static constexpr int SMEM_TOTAL = 66048;

// fp32 128x64 tile -> fp16, swizzled store
DI void load_f32_hi(const float* __restrict__ g, int lda, char* H, int tid) {
#pragma unroll
    for (int i = 0; i < 4; i++) {
        int q = tid + 256 * i, row = q >> 3, ck = q & 7;
        const float* p = g + (size_t)row * lda + ck * 8;
        float4 v0 = *(const float4*)p;
        float4 v1 = *(const float4*)(p + 4);
        float fv[8] = {v0.x, v0.y, v0.z, v0.w, v1.x, v1.y, v1.z, v1.w};
        uint32_t hp[4];
#pragma unroll
        for (int j = 0; j < 4; j++)
            hp[j] = pkh(__float2half_rn(fv[2 * j]), __float2half_rn(fv[2 * j + 1]));
        int off = row * 128 + ((ck ^ (row & 7)) << 4);
        *(uint4*)(H + off) = make_uint4(hp[0], hp[1], hp[2], hp[3]);
    }
}

// fp16 128x64 tile -> swizzled copy
DI void load_h16(const __half* __restrict__ g, int lda, char* D, int tid) {
#pragma unroll
    for (int i = 0; i < 4; i++) {
        int q = tid + 256 * i, row = q >> 3, ck = q & 7;
        int off = row * 128 + ((ck ^ (row & 7)) << 4);
        *(uint4*)(D + off) = *(const uint4*)(g + (size_t)row * lda + ck * 8);
    }
}

// One 64-wide K stage, single pass: acc += Ah.Bh
DI void compute_stage1(uint32_t smb, int buf, int wr, int wc, int lane, float acc[4][4][4]) {
    uint32_t Ah = smb + buf * STG;
    uint32_t Bh = Ah + 16384;
    const int ar = wr * 64 + (lane & 15);
    const int br = wc * 32 + (lane & 7) + ((lane & 16) >> 1);
    const int ax = lane & 7;
#pragma unroll
    for (int kk = 0; kk < 4; kk++) {
        const int ac = kk * 2 + (lane >> 4);
        const int bc = kk * 2 + ((lane >> 3) & 1);
        uint32_t ah[4][4], bh[4][2];
#pragma unroll
        for (int mt = 0; mt < 4; mt++)
            ldx4(ah[mt], Ah + (uint32_t)(ar + mt * 16) * 128 + (uint32_t)((ac ^ ax) << 4));
#pragma unroll
        for (int p = 0; p < 2; p++) {
            uint32_t off = (uint32_t)(br + p * 16) * 128 + (uint32_t)((bc ^ ax) << 4);
            uint32_t q[4];
            ldx4(q, Bh + off);
            bh[2 * p][0] = q[0]; bh[2 * p][1] = q[1];
            bh[2 * p + 1][0] = q[2]; bh[2 * p + 1][1] = q[3];
        }
#pragma unroll
        for (int mt = 0; mt < 4; mt++)
#pragma unroll
            for (int nt = 0; nt < 4; nt++) mma16816(acc[mt][nt], ah[mt], bh[nt]);
    }
}

// acc -> padded smem transpose
DI void epilogue_to_smem(float* eps, int wr, int wc, int lane, float acc[4][4][4]) {
#pragma unroll
    for (int mt = 0; mt < 4; mt++)
#pragma unroll
        for (int nt = 0; nt < 4; nt++) {
            int m = wr * 64 + mt * 16 + (lane >> 2);
            int n = wc * 32 + nt * 8 + (lane & 3) * 2;
            eps[m * 129 + n]           = acc[mt][nt][0];
            eps[m * 129 + n + 1]       = acc[mt][nt][1];
            eps[(m + 8) * 129 + n]     = acc[mt][nt][2];
            eps[(m + 8) * 129 + n + 1] = acc[mt][nt][3];
        }
}

// ===== GEMM1: w[b][n][o] = f[b,n,:].W_lin[o,:] + b_lin[o]; out fp16 =====
__global__ void __launch_bounds__(256, 2)
gemm1_kernel(const float* __restrict__ W, const float* __restrict__ f,
             const float* __restrict__ bias) {
    extern __shared__ char sm[];
    uint32_t smb = s2u(sm);
    const int m0 = blockIdx.x * 128, n0 = blockIdx.y * 128, b = blockIdx.z;
    const int tid = threadIdx.x, w = tid >> 5, lane = tid & 31;
    const int wr = w >> 2, wc = w & 3;
    const float* Abase = W + (size_t)m0 * HH;
    const float* Bbase = f + ((size_t)b * NN + n0) * HH;

    float acc[4][4][4];
#pragma unroll
    for (int i = 0; i < 4; i++)
#pragma unroll
        for (int j = 0; j < 4; j++)
#pragma unroll
            for (int c = 0; c < 4; c++) acc[i][j][c] = 0.f;

    load_f32_hi(Abase, HH, sm, tid);
    load_f32_hi(Bbase, HH, sm + 16384, tid);
    __syncthreads();

    const int NS = HH / 64;  // 16
    for (int s = 0; s < NS; s++) {
        if (s + 1 < NS) {
            char* nb = sm + ((s + 1) & 1) * STG;
            load_f32_hi(Abase + (s + 1) * 64, HH, nb, tid);
            load_f32_hi(Bbase + (s + 1) * 64, HH, nb + 16384, tid);
        }
        compute_stage1(smb, s & 1, wr, wc, lane, acc);
        __syncthreads();
    }

    float* eps = (float*)sm;
    epilogue_to_smem(eps, wr, wc, lane, acc);
    __syncthreads();

    const int m = tid & 127, nh = (tid >> 7) * 64;
    const float bv = bias[m0 + m];
    __half* oh = g_w_hi + ((size_t)b * NN + n0) * OO + m0 + m;
#pragma unroll 8
    for (int j = 0; j < 64; j++) {
        int n = nh + j;
        oh[(size_t)n * OO] = __float2half_rn(eps[m * 129 + n] + bv);
    }
}

// ===== GEMM2: pre[b][n][h] = kt[b,h,:].w[b,n,:] =====
__global__ void __launch_bounds__(256, 2)
gemm2_kernel() {
    extern __shared__ char sm[];
    uint32_t smb = s2u(sm);
    const int m0 = blockIdx.x * 128, n0 = blockIdx.y * 128, b = blockIdx.z;
    const int tid = threadIdx.x, w = tid >> 5, lane = tid & 31;
    const int wr = w >> 2, wc = w & 3;
    const __half* Abase = g_kt_hi + ((size_t)b * HH + m0) * OO;
    const __half* Bbase = g_w_hi + ((size_t)b * NN + n0) * OO;

    float acc[4][4][4];
#pragma unroll
    for (int i = 0; i < 4; i++)
#pragma unroll
        for (int j = 0; j < 4; j++)
#pragma unroll
            for (int c = 0; c < 4; c++) acc[i][j][c] = 0.f;

    load_h16(Abase, OO, sm, tid);
    load_h16(Bbase, OO, sm + 16384, tid);
    __syncthreads();

    const int NS = OO / 64;  // 12
    for (int s = 0; s < NS; s++) {
        if (s + 1 < NS) {
            char* nb = sm + ((s + 1) & 1) * STG;
            load_h16(Abase + (s + 1) * 64, OO, nb, tid);
            load_h16(Bbase + (s + 1) * 64, OO, nb + 16384, tid);
        }
        compute_stage1(smb, s & 1, wr, wc, lane, acc);
        __syncthreads();
    }

    float* eps = (float*)sm;
    epilogue_to_smem(eps, wr, wc, lane, acc);
    __syncthreads();

    const int m = tid & 127, nh = (tid >> 7) * 64;
    float* ob = g_pre + ((size_t)b * NN + n0) * HH + m0 + m;
#pragma unroll 8
    for (int j = 0; j < 64; j++) {
        int n = nh + j;
        ob[(size_t)n * HH] = eps[m * 129 + n];
    }
}

// kt[b][h][o] = fp16( k[b][o/3][h + o%3 - 1] ), zero-padded.
__global__ void __launch_bounds__(256)
ktbuild_kernel(const float* __restrict__ k) {
    __shared__ float sm[64][68];
    const int b = blockIdx.z, nin0 = blockIdx.x * 64, h0 = blockIdx.y * 64;
    const int tid = threadIdx.x;
    for (int idx = tid; idx < 64 * 66; idx += 256) {
        int i = idx / 66, c = idx % 66, h = h0 + c - 1;
        sm[i][c] = (h >= 0 && h < HH) ? k[((size_t)b * NN + nin0 + i) * HH + h] : 0.f;
    }
    __syncthreads();
    __half* dst = g_kt_hi + ((size_t)b * HH + h0) * OO + 3 * nin0;
    for (int idx = tid; idx < 64 * 96; idx += 256) {
        int j = idx / 96, p = idx % 96;
        int c0 = 2 * p, c1 = c0 + 1;
        int i0 = c0 / 3, d0 = c0 - 3 * i0;
        int i1 = c1 / 3, d1 = c1 - 3 * i1;
        *(__half2*)(dst + (size_t)j * OO + c0) =
            __floats2half2_rn(sm[i0][j + d0], sm[i1][j + d1]);
    }
}

// LayerNorm over H per (b,n) row
__global__ void __launch_bounds__(256)
ln_kernel(const float* __restrict__ gamma, const float* __restrict__ beta,
          float* __restrict__ out) {
    const int row = blockIdx.x, tid = threadIdx.x;
    const float* x = g_pre + (size_t)row * HH;
    float4 v = *(const float4*)(x + tid * 4);
    float s = v.x + v.y + v.z + v.w;
    float q = v.x * v.x + v.y * v.y + v.z * v.z + v.w * v.w;
#pragma unroll
    for (int o = 16; o; o >>= 1) {
        s += __shfl_xor_sync(0xFFFFFFFFu, s, o);
        q += __shfl_xor_sync(0xFFFFFFFFu, q, o);
    }
    __shared__ float ss[8], sq[8], red[2];
    if ((tid & 31) == 0) { ss[tid >> 5] = s; sq[tid >> 5] = q; }
    __syncthreads();
    if (tid == 0) {
        float S = 0.f, Q = 0.f;
#pragma unroll
        for (int i = 0; i < 8; i++) { S += ss[i]; Q += sq[i]; }
        float mu = S * (1.0f / HH);
        float var = Q * (1.0f / HH) - mu * mu;
        red[0] = mu;
        red[1] = rsqrtf(var + 1e-5f);
    }
    __syncthreads();
    const float mu = red[0], rinv = red[1];
    const int h = tid * 4;
    float4 g = *(const float4*)(gamma + h);
    float4 bt = *(const float4*)(beta + h);
    float4 y;
    y.x = (v.x - mu) * rinv * g.x + bt.x;
    y.y = (v.y - mu) * rinv * g.y + bt.y;
    y.z = (v.z - mu) * rinv * g.z + bt.z;
    y.w = (v.w - mu) * rinv * g.w + bt.w;
    *(float4*)(out + (size_t)row * HH + h) = y;
}

extern "C" void kernel_launch(void* const* d_in, const int* in_sizes, int n_in,
                              void* d_out, int out_size) {
    const float* f  = (const float*)d_in[0];
    const float* k  = (const float*)d_in[1];
    const float* W  = (const float*)d_in[2];
    const float* bl = (const float*)d_in[3];
    const float* gm = (const float*)d_in[4];
    const float* bt = (const float*)d_in[5];
    float* out = (float*)d_out;

    cudaFuncSetAttribute(gemm1_kernel, cudaFuncAttributeMaxDynamicSharedMemorySize, SMEM_TOTAL);
    cudaFuncSetAttribute(gemm2_kernel, cudaFuncAttributeMaxDynamicSharedMemorySize, SMEM_TOTAL);

    ktbuild_kernel<<<dim3(4, 16, BB), 256>>>(k);
    gemm1_kernel<<<dim3(OO / 128, NN / 128, BB), 256, SMEM_TOTAL>>>(W, f, bl);
    gemm2_kernel<<<dim3(HH / 128, NN / 128, BB), 256, SMEM_TOTAL>>>();
    ln_kernel<<<BB * NN, 256>>>(gm, bt, out);
}